// round 14
// baseline (speedup 1.0000x reference)
#include <cuda_runtime.h>
#include <cuda.h>
#include <cuda_bf16.h>
#include <cstdint>

// ---------------------------------------------------------------------------
// Problem constants
// ---------------------------------------------------------------------------
#define D_IN   992
#define HID    32
#define NKS    62            // 992 / 16 k-steps
#define NTILES 31            // 992 / 32 cols per TMA tile
#define TMROWS 128           // rows per CTA (8 warps x 1 m-tile)
#define STAGES 4

// W in mma B-fragment layout (k-permuted), bf16 hi/lo packed per lane:
// [ks 62][nt 4][lane 32] -> uint4 (bh0, bh1, bl0, bl1)
__device__ uint4 g_Wf[NKS * 4 * 32];

// ---------------------------------------------------------------------------
// dynamic smem layout (floats)
// ring: 4 stages x 4096 floats (16KB each).  After the mainloop the ring is
// dead; hs/pp overlay it.  KAN tables + mbarriers live beyond the ring.
// ---------------------------------------------------------------------------
#define SM_RING 0                          // 4*4096 = 16384 floats (64KB)
#define SM_HS   0                          // 128*33 = 4224 (overlays dead ring)
#define SM_PP   4224                       // 128*33 = 4224 (overlays dead ring)
#define SM_CW0  16384                      // 32*20*6 = 3840
#define SM_WB0  20224                      // 192
#define SM_CW1  20416                      // 120
#define SM_WB1  20536                      // 6
#define SM_B0   20542                      // 6
#define SM_B1   20548                      // 1 (+3 pad)
#define SM_MB   20552                      // 4 stages x (full,empty) x 8B = 16 floats
#define SM_TOTF 20568
#define SM_BYTES (SM_TOTF * 4)             // 82272 -> 2 CTAs/SM

#define STAGE_BYTES 16384

// ---------------------------------------------------------------------------
// helpers
// ---------------------------------------------------------------------------
__device__ __forceinline__ uint32_t smem_u32(const void* p) {
    uint32_t a;
    asm("{ .reg .u64 t; cvta.to.shared.u64 t, %1; cvt.u32.u64 %0, t; }"
        : "=r"(a) : "l"(p));
    return a;
}
__device__ __forceinline__ uint32_t packbf(float e0, float e1) {
    uint32_t r;
    asm("cvt.rn.bf16x2.f32 %0, %1, %2;" : "=r"(r) : "f"(e1), "f"(e0));
    return r;
}
__device__ __forceinline__ void unpackbf(uint32_t p, float& e0, float& e1) {
    e0 = __uint_as_float(p << 16);
    e1 = __uint_as_float(p & 0xFFFF0000u);
}
__device__ __forceinline__ void mma_bf16(float d[4], uint32_t a0, uint32_t a1,
                                         uint32_t a2, uint32_t a3,
                                         uint32_t b0, uint32_t b1) {
    asm volatile(
        "mma.sync.aligned.m16n8k16.row.col.f32.bf16.bf16.f32 "
        "{%0,%1,%2,%3}, {%4,%5,%6,%7}, {%8,%9}, {%0,%1,%2,%3};"
        : "+f"(d[0]), "+f"(d[1]), "+f"(d[2]), "+f"(d[3])
        : "r"(a0), "r"(a1), "r"(a2), "r"(a3), "r"(b0), "r"(b1));
}

#define MBAR_INIT(a, n) \
    asm volatile("mbarrier.init.shared.b64 [%0], %1;" :: "r"(a), "r"((uint32_t)(n)) : "memory")
#define MBAR_EXPECT_TX(a, bytes) \
    asm volatile("mbarrier.arrive.expect_tx.shared.b64 _, [%0], %1;" \
                 :: "r"(a), "r"((uint32_t)(bytes)) : "memory")
#define MBAR_ARRIVE(a) \
    asm volatile("mbarrier.arrive.shared.b64 _, [%0];" :: "r"(a) : "memory")
#define MBAR_WAIT(a, ph) do {                                                  \
    uint32_t _m = (a), _p = (uint32_t)(ph), _d;                                \
    asm volatile("{\n\t.reg .pred p;\n\t"                                      \
        "mbarrier.try_wait.parity.acquire.cta.shared::cta.b64 p, [%1], %2;\n\t"\
        "selp.b32 %0, 1, 0, p;\n\t}" : "=r"(_d) : "r"(_m), "r"(_p) : "memory");\
    if (!_d) {                                                                 \
        asm volatile("{\n\t.reg .pred P1;\n\t"                                 \
        "W%=:\n\t"                                                             \
        "mbarrier.try_wait.parity.acquire.cta.shared::cta.b64 P1, [%0], %1, 0x989680;\n\t" \
        "@P1 bra.uni D%=;\n\t bra.uni W%=;\n\tD%=:\n\t}"                       \
        :: "r"(_m), "r"(_p) : "memory");                                       \
    }                                                                          \
} while (0)

#define TMA_LOAD_2D(dst, tmap, cx, cy, mbar) \
    asm volatile("cp.async.bulk.tensor.2d.shared::cta.global.tile.mbarrier::complete_tx::bytes " \
        "[%0], [%1, {%2, %3}], [%4];" \
        :: "r"(dst), "l"(tmap), "r"((int)(cx)), "r"((int)(cy)), "r"(mbar) : "memory")

// f32x2 packed helpers (KAN phase)
__device__ __forceinline__ uint64_t f2dup(float x) {
    uint64_t r; asm("mov.b64 %0, {%1, %1};" : "=l"(r) : "f"(x)); return r;
}
__device__ __forceinline__ void f2unpack(uint64_t v, float& x, float& y) {
    asm("mov.b64 {%0, %1}, %2;" : "=f"(x), "=f"(y) : "l"(v));
}
__device__ __forceinline__ void ffma2(uint64_t& d, uint64_t a, uint64_t b) {
    asm("fma.rn.f32x2 %0, %1, %2, %0;" : "+l"(d) : "l"(a), "l"(b));
}

// degree-4 uniform B-spline basis (5 nonzero values), matches reference
__device__ __forceinline__ void bspline4(float u, float bw[5]) {
    const float um = 1.f - u;
    float c0 = um, c1 = u;
    float d0 = 0.5f * (um * c0);
    float d1 = 0.5f * ((u + 1.f) * c0 + (2.f - u) * c1);
    float d2 = 0.5f * (u * c1);
    const float i3 = 1.f / 3.f;
    float e0 = i3 * (um * d0);
    float e1 = i3 * ((u + 2.f) * d0 + (2.f - u) * d1);
    float e2 = i3 * ((u + 1.f) * d1 + (3.f - u) * d2);
    float e3 = i3 * (u * d2);
    bw[0] = 0.25f * (um * e0);
    bw[1] = 0.25f * ((u + 3.f) * e0 + (2.f - u) * e1);
    bw[2] = 0.25f * ((u + 2.f) * e1 + (3.f - u) * e2);
    bw[3] = 0.25f * ((u + 1.f) * e2 + (4.f - u) * e3);
    bw[4] = 0.25f * (u * e3);
}
__device__ __forceinline__ float silu_f(float x) { return x / (1.f + __expf(-x)); }

// ---------------------------------------------------------------------------
// W pre-conversion with k-permutation:
// lane (g,t4), nt: b0 = {W[ks16+4t4][n], W[ks16+4t4+1][n]},
//                  b1 = {W[ks16+4t4+2][n], W[ks16+4t4+3][n]}, n = nt*8+g
// ---------------------------------------------------------------------------
__global__ void wfrag_kernel(const float* __restrict__ W) {
    int idx = blockIdx.x * 256 + threadIdx.x;     // 62*4*32 = 7936
    if (idx >= NKS * 4 * 32) return;
    int lane = idx & 31;
    int nt   = (idx >> 5) & 3;
    int ks   = idx >> 7;
    int g = lane >> 2, t4 = lane & 3;
    int n  = nt * 8 + g;
    int ka = ks * 16 + t4 * 4;

    float x0 = W[(ka + 0) * HID + n];
    float x1 = W[(ka + 1) * HID + n];
    float y0 = W[(ka + 2) * HID + n];
    float y1 = W[(ka + 3) * HID + n];

    uint32_t h0 = packbf(x0, x1), h1 = packbf(y0, y1);
    float e0, e1;
    unpackbf(h0, e0, e1);
    uint32_t l0 = packbf(x0 - e0, x1 - e1);
    unpackbf(h1, e0, e1);
    uint32_t l1 = packbf(y0 - e0, y1 - e1);

    g_Wf[idx] = make_uint4(h0, h1, l0, l1);
}

// ---------------------------------------------------------------------------
// One k-sub-step of tile T (SUB in {0,1}).  W via LDG (L1-resident — no other
// L1 traffic in the loop), A via swizzled LDS from the ring stage, 12 mma.
// TMA SW128 on 128B rows: 16B unit u of row r stored at unit u ^ (r & 7).
// ---------------------------------------------------------------------------
#define GEMM_SUB(T, SUB)                                                       \
{                                                                              \
    const int _ks = 2 * (T) + (SUB);                                           \
    uint4 w[4];                                                                \
    {                                                                          \
        const uint4* wq = &g_Wf[(size_t)(_ks * 4) * 32 + lane];                \
        _Pragma("unroll")                                                      \
        for (int nt = 0; nt < 4; nt++) w[nt] = wq[nt * 32];                    \
    }                                                                          \
    const float* sb = ring + ((T) & (STAGES - 1)) * 4096;                      \
    const int _u = (((SUB) * 4 + t4) ^ g) << 2;                                \
    float4 a0 = *(const float4*)&sb[rl0 * 32 + _u];                            \
    float4 a1 = *(const float4*)&sb[rl1 * 32 + _u];                            \
    uint32_t ah0 = packbf(a0.x, a0.y);                                         \
    uint32_t ah1 = packbf(a1.x, a1.y);                                         \
    uint32_t ah2 = packbf(a0.z, a0.w);                                         \
    uint32_t ah3 = packbf(a1.z, a1.w);                                         \
    float e0, e1;                                                              \
    uint32_t al0, al1, al2, al3;                                               \
    unpackbf(ah0, e0, e1); al0 = packbf(a0.x - e0, a0.y - e1);                 \
    unpackbf(ah1, e0, e1); al1 = packbf(a1.x - e0, a1.y - e1);                 \
    unpackbf(ah2, e0, e1); al2 = packbf(a0.z - e0, a0.w - e1);                 \
    unpackbf(ah3, e0, e1); al3 = packbf(a1.z - e0, a1.w - e1);                 \
    _Pragma("unroll")                                                          \
    for (int nt = 0; nt < 4; nt++) {                                           \
        mma_bf16(acc[nt], ah0, ah1, ah2, ah3, w[nt].x, w[nt].y);               \
        mma_bf16(acc[nt], ah0, ah1, ah2, ah3, w[nt].z, w[nt].w);               \
        mma_bf16(acc[nt], al0, al1, al2, al3, w[nt].x, w[nt].y);               \
    }                                                                          \
}

// ---------------------------------------------------------------------------
// Fused kernel: TMA-staged A (4-stage mbarrier ring, tid0 producer, issue
// distance 3), 8 warps x 1 m-tile, accumulators persist across all tiles.
// ---------------------------------------------------------------------------
__global__ void __launch_bounds__(256, 2)
fused_kernel(const __grid_constant__ CUtensorMap tmap,
             const float* __restrict__ bias,
             const float* __restrict__ coef0, const float* __restrict__ wb0,
             const float* __restrict__ ws0,   const float* __restrict__ b0,
             const float* __restrict__ coef1, const float* __restrict__ wb1,
             const float* __restrict__ ws1,   const float* __restrict__ b1,
             float* __restrict__ out, int N)
{
    extern __shared__ __align__(16) float smem[];
    float* ring = smem + SM_RING;
    float* hs   = smem + SM_HS;            // overlays dead ring
    float* pp   = smem + SM_PP;            // overlays dead ring
    float* cw0p = smem + SM_CW0;
    float* wb0s = smem + SM_WB0;
    float* cw1p = smem + SM_CW1;
    float* wb1s = smem + SM_WB1;
    float* b0s  = smem + SM_B0;
    float* b1s  = smem + SM_B1;

    const int tid  = threadIdx.x;
    const int warp = tid >> 5;             // m-tile id (rows warp*16..+15)
    const int lane = tid & 31;
    const int g    = lane >> 2;
    const int t4   = lane & 3;
    const int row0 = blockIdx.x * TMROWS;
    const int rl0  = warp * 16 + g;
    const int rl1  = rl0 + 8;

    const uint32_t ring_a = smem_u32(ring);
    const uint32_t mb     = smem_u32(smem + SM_MB);
    // full(s) = mb + s*16, empty(s) = mb + s*16 + 8

    // ---- mbarrier init ----
    if (tid == 0) {
        #pragma unroll
        for (int s = 0; s < STAGES; s++) {
            MBAR_INIT(mb + s * 16,     1);     // full: expect_tx arrival
            MBAR_INIT(mb + s * 16 + 8, 256);   // empty: all threads arrive
        }
    }

    // ---- stage KAN tables (zero-padded j range: jj = j+4 in 0..19) ----
    for (int idx = tid; idx < 32 * 20 * 6; idx += 256) {
        int i = idx / 120, rem = idx % 120, jj = rem / 6, o = rem % 6;
        int j = jj - 4;
        cw0p[idx] = (j >= 0 && j < 12)
                  ? coef0[(i * 6 + o) * 12 + j] * ws0[i * 6 + o] : 0.f;
    }
    if (tid < 32 * 6) wb0s[tid] = wb0[tid];
    if (tid < 120) {
        int i = tid / 20, jj = tid % 20, j = jj - 4;
        cw1p[tid] = (j >= 0 && j < 12) ? coef1[i * 12 + j] * ws1[i] : 0.f;
    }
    if (tid < 6)  { wb1s[tid] = wb1[tid]; b0s[tid] = b0[tid]; }
    if (tid == 0) b1s[0] = b1[0];

    __syncthreads();   // mbarrier init visible to all before any wait/arrive

    // ---- pre-issue tiles 0..2 (round 0: no empty wait needed) ----
    if (tid == 0) {
        #pragma unroll
        for (int ti = 0; ti < STAGES - 1; ti++) {
            MBAR_EXPECT_TX(mb + ti * 16, STAGE_BYTES);
            TMA_LOAD_2D(ring_a + ti * STAGE_BYTES, &tmap, ti * 32, row0,
                        mb + ti * 16);
        }
    }

    float acc[4][4];
    #pragma unroll
    for (int nt = 0; nt < 4; nt++)
        #pragma unroll
        for (int r = 0; r < 4; r++) acc[nt][r] = 0.f;

    // ---- mainloop: 31 tiles, no __syncthreads ----
    for (int t = 0; t < NTILES; t++) {
        // producer: issue tile t+3
        if (tid == 0) {
            const int ti = t + STAGES - 1;
            if (ti < NTILES) {
                const int sl = ti & (STAGES - 1);
                const int rd = ti >> 2;                // issue round for slot
                if (rd > 0) MBAR_WAIT(mb + sl * 16 + 8, (rd - 1) & 1);
                MBAR_EXPECT_TX(mb + sl * 16, STAGE_BYTES);
                TMA_LOAD_2D(ring_a + sl * STAGE_BYTES, &tmap, ti * 32, row0,
                            mb + sl * 16);
            }
        }
        // consumer: wait tile t, consume 2 k-steps, release
        const int slot = t & (STAGES - 1);
        MBAR_WAIT(mb + slot * 16, (t >> 2) & 1);
        GEMM_SUB(t, 0);
        GEMM_SUB(t, 1);
        MBAR_ARRIVE(mb + slot * 16 + 8);
    }

    // ---- epilogue: bias add + transpose (ring dead; hs overlays it) ----
    __syncthreads();
    #pragma unroll
    for (int nt = 0; nt < 4; nt++) {
        float2 bv = *(const float2*)&bias[nt * 8 + t4 * 2];
        int c0 = nt * 8 + t4 * 2;
        hs[rl0 * 33 + c0]     = acc[nt][0] + bv.x;
        hs[rl0 * 33 + c0 + 1] = acc[nt][1] + bv.y;
        hs[rl1 * 33 + c0]     = acc[nt][2] + bv.x;
        hs[rl1 * 33 + c0 + 1] = acc[nt][3] + bv.y;
    }
    __syncthreads();

    // ---- KAN layer 0: 2 threads per row, each handles 16 of 32 inputs ----
    const int r = tid & 127;
    const int h = tid >> 7;

    uint64_t kacc[3];
    kacc[0] = kacc[1] = kacc[2] = 0ull;

    #pragma unroll
    for (int i2 = 0; i2 < 16; i2++) {
        const int i = h * 16 + i2;
        float x  = hs[r * 33 + i];
        float sg = silu_f(x);
        uint64_t sgd = f2dup(sg);
        const uint64_t* wbp = (const uint64_t*)&wb0s[i * 6];
        ffma2(kacc[0], sgd, wbp[0]);
        ffma2(kacc[1], sgd, wbp[1]);
        ffma2(kacc[2], sgd, wbp[2]);

        float t = (x + 2.f) * 4.f;
        if (t >= 0.f && t < 16.f) {
            float cf = floorf(t);
            int   c  = (int)cf;
            float u  = t - cf;
            float bw[5];
            bspline4(u, bw);
            const float* base = &cw0p[i * 120 + c * 6];
            #pragma unroll
            for (int k = 0; k < 5; k++) {
                uint64_t bd = f2dup(bw[k]);
                const uint64_t* cp = (const uint64_t*)(base + k * 6);
                ffma2(kacc[0], bd, cp[0]);
                ffma2(kacc[1], bd, cp[1]);
                ffma2(kacc[2], bd, cp[2]);
            }
        }
    }
    __syncthreads();
    {
        float p0, p1, p2, p3, p4, p5;
        f2unpack(kacc[0], p0, p1);
        f2unpack(kacc[1], p2, p3);
        f2unpack(kacc[2], p4, p5);
        float* q = &pp[r * 12 + h * 6];
        q[0] = p0; q[1] = p1; q[2] = p2;
        q[3] = p3; q[4] = p4; q[5] = p5;
    }
    __syncthreads();

    // ---- KAN layer 1 (half 0 threads only) ----
    if (h == 0) {
        const int row = row0 + r;
        if (row < N) {
            float res = b1s[0];
            #pragma unroll
            for (int i = 0; i < 6; i++) {
                float x = pp[r * 12 + i] + pp[r * 12 + 6 + i] + b0s[i];
                res += silu_f(x) * wb1s[i];
                float t = (x + 2.f) * 4.f;
                if (t >= 0.f && t < 16.f) {
                    float cf = floorf(t);
                    int   c  = (int)cf;
                    float u  = t - cf;
                    float bw[5];
                    bspline4(u, bw);
                    const float* base = &cw1p[i * 20 + c];
                    #pragma unroll
                    for (int k = 0; k < 5; k++)
                        res += bw[k] * base[k];
                }
            }
            out[row] = res;
        }
    }
}

// ---------------------------------------------------------------------------
// Launch
// ---------------------------------------------------------------------------
typedef CUresult (*EncodeTiledFn)(
    CUtensorMap*, CUtensorMapDataType, cuuint32_t, void*,
    const cuuint64_t*, const cuuint64_t*, const cuuint32_t*, const cuuint32_t*,
    CUtensorMapInterleave, CUtensorMapSwizzle, CUtensorMapL2promotion,
    CUtensorMapFloatOOBfill);

extern "C" void kernel_launch(void* const* d_in, const int* in_sizes, int n_in,
                              void* d_out, int out_size)
{
    const float* node_rep = (const float*)d_in[0];
    const float* mlp_w    = (const float*)d_in[1];
    const float* mlp_b    = (const float*)d_in[2];
    const float* coef0    = (const float*)d_in[3];
    const float* wb0      = (const float*)d_in[4];
    const float* ws0      = (const float*)d_in[5];
    const float* b0       = (const float*)d_in[6];
    const float* coef1    = (const float*)d_in[7];
    const float* wb1      = (const float*)d_in[8];
    const float* ws1      = (const float*)d_in[9];
    const float* b1       = (const float*)d_in[10];

    int N = in_sizes[0] / D_IN;

    static EncodeTiledFn enc = nullptr;
    if (!enc) {
        cudaDriverEntryPointQueryResult qr;
        cudaGetDriverEntryPoint("cuTensorMapEncodeTiled", (void**)&enc,
                                cudaEnableDefault, &qr);
    }

    CUtensorMap tmap;
    cuuint64_t dims[2]    = {(cuuint64_t)D_IN, (cuuint64_t)N};
    cuuint64_t strides[1] = {(cuuint64_t)D_IN * sizeof(float)};
    cuuint32_t box[2]     = {32, 128};
    cuuint32_t es[2]      = {1, 1};
    enc(&tmap, CU_TENSOR_MAP_DATA_TYPE_FLOAT32, 2, (void*)node_rep,
        dims, strides, box, es,
        CU_TENSOR_MAP_INTERLEAVE_NONE, CU_TENSOR_MAP_SWIZZLE_128B,
        CU_TENSOR_MAP_L2_PROMOTION_L2_128B, CU_TENSOR_MAP_FLOAT_OOB_FILL_NONE);

    cudaFuncSetAttribute(fused_kernel,
                         cudaFuncAttributeMaxDynamicSharedMemorySize, SM_BYTES);

    wfrag_kernel<<<(NKS * 4 * 32 + 255) / 256, 256>>>(mlp_w);
    fused_kernel<<<(N + TMROWS - 1) / TMROWS, 256, SM_BYTES>>>(
        tmap, mlp_b, coef0, wb0, ws0, b0, coef1, wb1, ws1, b1,
        (float*)d_out, N);
}